// round 1
// baseline (speedup 1.0000x reference)
#include <cuda_runtime.h>
#include <math.h>

// ---------------------------------------------------------------------------
// EDR loss: irfft(96000) -> STFT(512/256, hann) -> suffix-sum dB -> L1 ratio
// N = 96000 = 375 * 256.  k = w + 375*m (w<375, m<256); t = 256*s1 + s2.
// ---------------------------------------------------------------------------

#define NFFT  96000
#define NHALF 48000
#define NSIG  256          // 2 signals * 128 batches
#define NW    375
#define NM    256
#define TFR   374
#define FBIN  257

// Scratch (static device globals: the sanctioned no-alloc workaround)
__device__ float2 g_G[(size_t)NSIG * NM * NW];      // [p][s2][w]   196.6 MB
__device__ float  g_y[(size_t)NSIG * NFFT];         // [p][t]        98.3 MB
__device__ float  g_P[(size_t)NSIG * TFR * FBIN];   // [p][m][f]     98.4 MB
__device__ float2 g_tw96000[NFFT];                  // e^{+2pi i j/96000}
__device__ float2 g_tw512[512];                     // e^{-2pi i j/512}
__device__ float  g_win[512];                       // periodic hann
__device__ double g_pnum[128];
__device__ double g_pden[128];

__device__ __forceinline__ float2 cmul(float2 a, float2 b) {
    return make_float2(fmaf(a.x, b.x, -a.y * b.y), fmaf(a.x, b.y, a.y * b.x));
}
__device__ __forceinline__ float2 cfma(float2 a, float2 b, float2 c) {
    c.x = fmaf(a.x, b.x, fmaf(-a.y, b.y, c.x));
    c.y = fmaf(a.x, b.y, fmaf( a.y, b.x, c.y));
    return c;
}

// ---------------------------------------------------------------------------
__global__ void build_tables_kernel() {
    int i = blockIdx.x * blockDim.x + threadIdx.x;
    if (i < NFFT) {
        double a = (2.0 * M_PI / (double)NFFT) * (double)i;
        g_tw96000[i] = make_float2((float)cos(a), (float)sin(a));
    }
    if (i < 512) {
        double a = (2.0 * M_PI / 512.0) * (double)i;
        g_tw512[i] = make_float2((float)cos(a), (float)-sin(a));
        g_win[i]   = (float)(0.5 * (1.0 - cos(a)));
    }
}

// ---------------------------------------------------------------------------
// Pass 1: per signal p, for each w in [0,375): 256-pt FFT over m of real
// C[w+375m], evaluated at s2, times e^{+2pi i w s2/96000}. C[k]=X[min(k,N-k)].
// 256-pt FFT as 16x16: m=16*m1+m2, s2=s2a+16*s2b.
// Dynamic smem: Xs[48008] + Ascr[8*256 c] + tile[256*8 c] + tw16p[16 c]
// ---------------------------------------------------------------------------
#define P1_SMEM (48008*4 + 8*256*8 + 256*8*8 + 16*8)

__global__ void __launch_bounds__(256) pass1_kernel(const float* __restrict__ tgt,
                                                    const float* __restrict__ ach) {
    int p = blockIdx.x;
    const float* X = ((p >> 7) ? ach : tgt) + (size_t)(p & 127) * NFFT;

    extern __shared__ float sm[];
    float*  Xs    = sm;                              // 48008 floats
    float2* Ascr  = (float2*)(sm + 48008);           // 8 * 256
    float2* tile  = Ascr + 8 * 256;                  // [s2][8]
    float2* tw16p = tile + 256 * 8;                  // 16

    int tid = threadIdx.x;
    for (int i = tid; i <= NHALF; i += 256) Xs[i] = X[i];
    if (tid < 16) tw16p[tid] = g_tw96000[6000 * tid];   // e^{+2pi i j/16}
    __syncthreads();

    int warp = tid >> 5, lane = tid & 31;
    float2* A = Ascr + warp * 256;
    float2* Gp = g_G + (size_t)p * NM * NW;

    for (int w0 = 0; w0 < NW; w0 += 8) {
        int w = w0 + warp;
        if (w < NW) {
            // Stage A: A[s2a][m2] = sum_m1 C[w+375*(16m1+m2)] e^{+2pi i m1 s2a/16}
            for (int i = lane; i < 256; i += 32) {
                int s2a = i >> 4, m2 = i & 15;
                float re = 0.f, im = 0.f;
                int kbase = w + 375 * m2;
#pragma unroll
                for (int m1 = 0; m1 < 16; m1++) {
                    int k = kbase + 6000 * m1;
                    float c = Xs[(k <= NHALF) ? k : (NFFT - k)];
                    float2 t = tw16p[(m1 * s2a) & 15];
                    re = fmaf(c, t.x, re);
                    im = fmaf(c, t.y, im);
                }
                // twiddle e^{+2pi i m2 s2a/256}
                float2 t2 = g_tw96000[375 * (m2 * s2a)];
                A[i] = make_float2(fmaf(re, t2.x, -im * t2.y),
                                   fmaf(re, t2.y,  im * t2.x));
            }
            __syncwarp();
            // Stage B: g[s2] = sum_m2 A[s2a][m2] e^{+2pi i m2 s2b/16}, outer twiddle
            for (int s2 = lane; s2 < 256; s2 += 32) {
                int s2a = s2 & 15, s2b = s2 >> 4;
                float2 acc = make_float2(0.f, 0.f);
                const float2* Ar = A + s2a * 16;
#pragma unroll
                for (int m2 = 0; m2 < 16; m2++)
                    acc = cfma(Ar[m2], tw16p[(m2 * s2b) & 15], acc);
                float2 tw = g_tw96000[w * s2];   // <= 374*255 < 96000
                tile[s2 * 8 + warp] = cmul(acc, tw);
            }
        }
        __syncthreads();
        int wn = min(8, NW - w0);
        for (int i = tid; i < 256 * 8; i += 256) {
            int s2 = i >> 3, j = i & 7;
            if (j < wn) Gp[(size_t)s2 * NW + w0 + j] = tile[i];
        }
        __syncthreads();
    }
}

// ---------------------------------------------------------------------------
// Pass 2: per (p, s2): y[256*s1+s2] = Re( sum_w G[p][s2][w] e^{+2pi i w s1/375} )/N
// 375 = 15*25: w = 25*w1 + w2, s1 = s1a + 15*s1b.
// Block handles 8 consecutive s2 (one per warp).
// ---------------------------------------------------------------------------
#define P2_SMEM (8*375*8*2 + 375*8*4 + (15+25)*8)

__global__ void __launch_bounds__(256) pass2_kernel() {
    int p   = blockIdx.y;
    int s20 = blockIdx.x * 8;

    extern __shared__ float sm2[];
    float2* Grow = (float2*)sm2;                 // 8*375
    float2* Bsh  = Grow + 8 * 375;               // 8*375
    float*  yt   = (float*)(Bsh + 8 * 375);      // [s1][8]
    float2* tw15 = (float2*)(yt + 375 * 8);      // 15
    float2* tw25 = tw15 + 15;                    // 25

    int tid = threadIdx.x;
    if (tid < 15) tw15[tid] = g_tw96000[6400 * tid];
    if (tid < 25) tw25[tid] = g_tw96000[3840 * tid];

    const float2* Gp = g_G + (size_t)p * NM * NW;
    for (int i = tid; i < 8 * 375; i += 256) {
        int s2l = i / 375, w = i - s2l * 375;
        Grow[s2l * 375 + w] = Gp[(size_t)(s20 + s2l) * NW + w];
    }
    __syncthreads();

    int warp = tid >> 5, lane = tid & 31;
    const float2* Gr = Grow + warp * 375;
    float2* Br = Bsh + warp * 375;

    // Stage A: B[s1a][w2] = sum_w1 G[25w1+w2] e^{+2pi i w1 s1a/15}, tw e^{+2pi i w2 s1a/375}
    for (int i = lane; i < 375; i += 32) {
        int s1a = i / 25, w2 = i - s1a * 25;
        float2 acc = make_float2(0.f, 0.f);
        int t = 0;
#pragma unroll
        for (int w1 = 0; w1 < 15; w1++) {
            acc = cfma(Gr[25 * w1 + w2], tw15[t], acc);
            t += s1a; if (t >= 15) t -= 15;
        }
        float2 t2 = g_tw96000[256 * (w2 * s1a)];   // w2*s1a <= 336
        Br[i] = cmul(acc, t2);
    }
    __syncwarp();

    const float inv = 1.0f / (float)NFFT;
    for (int s1 = lane; s1 < 375; s1 += 32) {
        int s1a = s1 % 15, s1b = s1 / 15;
        const float2* Bp = Br + s1a * 25;
        float re = 0.f;
        int t = 0;
#pragma unroll
        for (int w2 = 0; w2 < 25; w2++) {
            float2 tw = tw25[t];
            re = fmaf(Bp[w2].x, tw.x, re);
            re = fmaf(-Bp[w2].y, tw.y, re);
            t += s1b; if (t >= 25) t -= 25;
        }
        yt[s1 * 8 + warp] = re * inv;
    }
    __syncthreads();

    float* yp = g_y + (size_t)p * NFFT;
    for (int i = tid; i < 375 * 8; i += 256) {
        int s1 = i >> 3, j = i & 7;
        yp[256 * s1 + s20 + j] = yt[i];
    }
}

// ---------------------------------------------------------------------------
// Pass 3: STFT. One warp per frame m: z[i] = y[t0+2i]*w[2i] + i*y[t0+2i+1]*w[2i+1],
// 256-pt forward FFT (16x16), Hermitian untangle -> |rfft512|^2 -> P[p][m][f].
// ---------------------------------------------------------------------------
__global__ void __launch_bounds__(256) pass3_kernel() {
    int p  = blockIdx.y;
    int m0 = blockIdx.x * 8;

    __shared__ float2 zsh[8][256];
    __shared__ float2 Ash[8][256];
    __shared__ float2 ctw16[16];
    __shared__ float2 tw512s[512];
    __shared__ float  wins[512];

    int tid = threadIdx.x;
    for (int i = tid; i < 512; i += 256) { tw512s[i] = g_tw512[i]; wins[i] = g_win[i]; }
    if (tid < 16) ctw16[tid] = g_tw512[32 * tid];   // e^{-2pi i j/16}
    __syncthreads();

    int warp = tid >> 5, lane = tid & 31;
    int m = m0 + warp;
    if (m < TFR) {
        const float* yp = g_y + (size_t)p * NFFT + 256 * m;
        float2* z  = zsh[warp];
        float2* Aa = Ash[warp];

        for (int i = lane; i < 256; i += 32) {
            float2 yv = *reinterpret_cast<const float2*>(yp + 2 * i);
            float2 wv = *reinterpret_cast<const float2*>(wins + 2 * i);
            z[i] = make_float2(yv.x * wv.x, yv.y * wv.y);
        }
        __syncwarp();

        for (int i = lane; i < 256; i += 32) {
            int ka = i >> 4, m2 = i & 15;
            float2 acc = make_float2(0.f, 0.f);
#pragma unroll
            for (int m1 = 0; m1 < 16; m1++)
                acc = cfma(z[16 * m1 + m2], ctw16[(m1 * ka) & 15], acc);
            float2 t2 = tw512s[2 * (m2 * ka)];     // e^{-2pi i m2 ka/256}
            Aa[i] = cmul(acc, t2);
        }
        __syncwarp();

        for (int k = lane; k < 256; k += 32) {
            int ka = k & 15, kb = k >> 4;
            float2 acc = make_float2(0.f, 0.f);
            const float2* Ar = Aa + ka * 16;
#pragma unroll
            for (int m2 = 0; m2 < 16; m2++)
                acc = cfma(Ar[m2], ctw16[(m2 * kb) & 15], acc);
            z[k] = acc;   // Z[k]
        }
        __syncwarp();

        float* Pp = g_P + ((size_t)p * TFR + m) * FBIN;
        for (int f = lane; f < FBIN; f += 32) {
            int k  = f & 255;
            int kc = (256 - k) & 255;
            float2 Z1 = z[k], Z2 = z[kc];
            float2 E = make_float2(0.5f * (Z1.x + Z2.x), 0.5f * (Z1.y - Z2.y));
            float2 O = make_float2(0.5f * (Z1.y + Z2.y), -0.5f * (Z1.x - Z2.x));
            float2 Wf = tw512s[f];                 // f <= 256
            float2 S = make_float2(E.x + Wf.x * O.x - Wf.y * O.y,
                                   E.y + Wf.x * O.y + Wf.y * O.x);
            Pp[f] = S.x * S.x + S.y * S.y;
        }
    }
}

// ---------------------------------------------------------------------------
// Pass 4: suffix sums along m, dB, |diff| and |target| partial sums per batch.
// Deterministic: block partials to global arrays, summed by final kernel.
// ---------------------------------------------------------------------------
__global__ void __launch_bounds__(288) pass4_kernel() {
    int b = blockIdx.x;
    int f = threadIdx.x;
    double num = 0.0, den = 0.0;
    if (f < FBIN) {
        const float* PT = g_P + (size_t)b * TFR * FBIN + f;
        const float* PA = g_P + (size_t)(128 + b) * TFR * FBIN + f;
        float accT = 0.f, accA = 0.f;
        for (int m = TFR - 1; m >= 0; m--) {
            accT += PT[(size_t)m * FBIN];
            accA += PA[(size_t)m * FBIN];
            float eT = 10.0f * log10f(accT);
            float eA = 10.0f * log10f(accA);
            num += (double)fabsf(eT - eA);
            den += (double)fabsf(eT);
        }
    }
    __shared__ double sn[288], sd[288];
    sn[threadIdx.x] = num;
    sd[threadIdx.x] = den;
    __syncthreads();
    if (threadIdx.x == 0) {
        double a = 0.0, c = 0.0;
        for (int i = 0; i < 288; i++) { a += sn[i]; c += sd[i]; }
        g_pnum[b] = a;
        g_pden[b] = c;
    }
}

__global__ void final_kernel(float* __restrict__ out) {
    double n = 0.0, d = 0.0;
    for (int i = 0; i < 128; i++) { n += g_pnum[i]; d += g_pden[i]; }
    out[0] = (float)(n / d);
}

// ---------------------------------------------------------------------------
extern "C" void kernel_launch(void* const* d_in, const int* in_sizes, int n_in,
                              void* d_out, int out_size) {
    const float* tgt = (const float*)d_in[0];
    const float* ach = (const float*)d_in[1];
    float* out = (float*)d_out;
    (void)in_sizes; (void)n_in; (void)out_size;

    cudaFuncSetAttribute(pass1_kernel, cudaFuncAttributeMaxDynamicSharedMemorySize, P1_SMEM);
    cudaFuncSetAttribute(pass2_kernel, cudaFuncAttributeMaxDynamicSharedMemorySize, P2_SMEM);

    build_tables_kernel<<<(NFFT + 255) / 256, 256>>>();
    pass1_kernel<<<NSIG, 256, P1_SMEM>>>(tgt, ach);
    pass2_kernel<<<dim3(NM / 8, NSIG), 256, P2_SMEM>>>();
    pass3_kernel<<<dim3((TFR + 7) / 8, NSIG), 256>>>();
    pass4_kernel<<<128, 288>>>();
    final_kernel<<<1, 1>>>(out);
}

// round 3
// speedup vs baseline: 1.9852x; 1.9852x over previous
#include <cuda_runtime.h>
#include <math.h>

// ---------------------------------------------------------------------------
// EDR loss: irfft(96000) -> STFT(512/256, hann) -> suffix-sum dB -> L1 ratio
// N = 96000 = 375 * 256.  k = w + 375*m (w<375, m<256); t = 256*s1 + s2.
// Packing: z[k] = Ct[k] + i*Ca[k] (both spectra real & even) -> one complex
// FFT per batch; Re -> target RIR, Im -> achieved RIR.
// ---------------------------------------------------------------------------

#define NFFT  96000
#define NHALF 48000
#define NB    128          // batches (complex-packed signals)
#define NSIG  256          // 2 * NB real signals (for y/P layout)
#define NW    375
#define NM    256
#define TFR   374
#define FBIN  257

// Scratch
__device__ float2 g_G[(size_t)NB * NW * NM];        // [p][w][s2]    98.3 MB
__device__ float  g_y[(size_t)NSIG * NFFT];         // [sig][t]      98.3 MB
__device__ float  g_P[(size_t)NSIG * TFR * FBIN];   // [sig][m][f]   98.4 MB
__device__ float2 g_tw96000[NFFT];                  // e^{+2pi i j/96000}
__device__ float2 g_tw512[512];                     // e^{-2pi i j/512}
__device__ float  g_win[512];                       // periodic hann
__device__ double g_pnum[128];
__device__ double g_pden[128];

__device__ __forceinline__ float2 cmul(float2 a, float2 b) {
    return make_float2(fmaf(a.x, b.x, -a.y * b.y), fmaf(a.x, b.y, a.y * b.x));
}
__device__ __forceinline__ float2 cfma(float2 a, float2 b, float2 c) {
    c.x = fmaf(a.x, b.x, fmaf(-a.y, b.y, c.x));
    c.y = fmaf(a.x, b.y, fmaf( a.y, b.x, c.y));
    return c;
}

// ---------------------------------------------------------------------------
__global__ void build_tables_kernel() {
    int i = blockIdx.x * blockDim.x + threadIdx.x;
    if (i < NFFT) {
        double a = (2.0 * M_PI / (double)NFFT) * (double)i;
        g_tw96000[i] = make_float2((float)cos(a), (float)sin(a));
    }
    if (i < 512) {
        double a = (2.0 * M_PI / 512.0) * (double)i;
        g_tw512[i] = make_float2((float)cos(a), (float)-sin(a));
        g_win[i]   = (float)(0.5 * (1.0 - cos(a)));
    }
}

// ---------------------------------------------------------------------------
// Pass 1: per (p, w): G[p][w][s2] = e^{+2pi i w s2/N} * FFT256_m(z[w+375m])[s2]
// 256-pt FFT as 16x16 (m = 16*m1 + m2, s2 = s2a + 16*s2b).
// One warp per w; 8 w per block; spectrum read directly from global
// (8 adjacent w per block -> full 32B-sector utilization via L1).
// ---------------------------------------------------------------------------
__global__ void __launch_bounds__(256) pass1_kernel(const float* __restrict__ tgt,
                                                    const float* __restrict__ ach) {
    __shared__ float2 zsh[8][256];
    __shared__ float2 Ash[8][16 * 17];     // padded rows: conflict-free stage B
    __shared__ float2 tw16s[16];           // e^{+2pi i j/16}
    __shared__ float2 tw256p[272];         // e^{+2pi i u/256} at u + (u>>4)

    int p  = blockIdx.y;
    int w0 = blockIdx.x * 8;
    int tid = threadIdx.x, warp = tid >> 5, lane = tid & 31;

    if (tid < 16) tw16s[tid] = g_tw96000[6000 * tid];
    { int u = tid; if (u < 256) tw256p[u + (u >> 4)] = g_tw96000[375 * u]; }

    int w = w0 + warp;
    const float* Xt = tgt + (size_t)p * NFFT;
    const float* Xa = ach + (size_t)p * NFFT;
    if (w < NW) {
        for (int m = lane; m < 256; m += 32) {
            int k = w + 375 * m;
            int r = (k <= NHALF) ? k : (NFFT - k);
            zsh[warp][m] = make_float2(__ldg(Xt + r), __ldg(Xa + r));
        }
    }
    __syncthreads();
    if (w >= NW) return;

    const float2* zr = zsh[warp];
    float2* Ar = Ash[warp];

    // Stage A: A[s2a][m2] = (sum_m1 z[16m1+m2] e^{+2pi i m1 s2a/16}) e^{+2pi i m2 s2a/256}
    for (int i = lane; i < 256; i += 32) {
        int s2a = i >> 4, m2 = i & 15;
        float2 a0 = make_float2(0.f, 0.f), a1 = make_float2(0.f, 0.f);
#pragma unroll
        for (int m1 = 0; m1 < 16; m1 += 2) {
            a0 = cfma(zr[16 * m1 + m2],       tw16s[(m1 * s2a) & 15],       a0);
            a1 = cfma(zr[16 * (m1 + 1) + m2], tw16s[((m1 + 1) * s2a) & 15], a1);
        }
        float2 acc = make_float2(a0.x + a1.x, a0.y + a1.y);
        int u = m2 * s2a;                       // <= 225
        Ar[s2a * 17 + m2] = cmul(acc, tw256p[u + (u >> 4)]);
    }
    __syncwarp();

    // Stage B + outer twiddle (recurrence) + direct coalesced global write
    float2 t    = g_tw96000[w * lane];          // e^{+2pi i w*lane/N}, < 96000
    float2 step = g_tw96000[32 * w];            // e^{+2pi i 32w/N}
    float2* Gout = g_G + ((size_t)p * NW + w) * NM;
    for (int s2 = lane; s2 < 256; s2 += 32) {
        int s2a = s2 & 15, s2b = s2 >> 4;
        float2 a0 = make_float2(0.f, 0.f), a1 = make_float2(0.f, 0.f);
        const float2* Arr = Ar + s2a * 17;
#pragma unroll
        for (int m2 = 0; m2 < 16; m2 += 2) {
            a0 = cfma(Arr[m2],     tw16s[(m2 * s2b) & 15],       a0);
            a1 = cfma(Arr[m2 + 1], tw16s[((m2 + 1) * s2b) & 15], a1);
        }
        float2 acc = make_float2(a0.x + a1.x, a0.y + a1.y);
        Gout[s2] = cmul(acc, t);
        t = cmul(t, step);
    }
}

// ---------------------------------------------------------------------------
// Pass 2: per (p, s2): Y[s1] = sum_w G[p][w][s2] e^{+2pi i w s1/375};
// y_t[256 s1 + s2] = Re(Y)/N, y_a = Im(Y)/N.  375 = 15*25.
// 8 s2 per block (one per warp).
// ---------------------------------------------------------------------------
#define P2_SMEM ((3375 + 3000 + 3375 + 15 + 25 + 360) * 8)

__global__ void __launch_bounds__(256) pass2_kernel() {
    int p   = blockIdx.y;
    int s20 = blockIdx.x * 8;

    extern __shared__ float2 sm2[];
    float2* Grow   = sm2;                 // [w][j], pad 9   (3375)
    float2* Bsh    = Grow + 3375;         // [j][375]        (3000)
    float2* ytile  = Bsh + 3000;          // [s1][j], pad 9  (3375)
    float2* tw15s  = ytile + 3375;        // 15
    float2* tw25s  = tw15s + 15;          // 25
    float2* tw375p = tw25s + 25;          // e^{+2pi i u/375} at u+(u>>4), 360

    int tid = threadIdx.x, warp = tid >> 5, lane = tid & 31;
    if (tid < 15) tw15s[tid] = g_tw96000[6400 * tid];
    if (tid < 25) tw25s[tid] = g_tw96000[3840 * tid];
    for (int u = tid; u < 337; u += 256) tw375p[u + (u >> 4)] = g_tw96000[256 * u];

    for (int i = tid; i < 3000; i += 256) {
        int w = i >> 3, j = i & 7;
        Grow[w * 9 + j] = g_G[((size_t)p * NW + w) * NM + s20 + j];
    }
    __syncthreads();

    // Stage A: B[s1a][w2] = (sum_w1 G[25w1+w2] e^{+2pi i w1 s1a/15}) e^{+2pi i w2 s1a/375}
    float2* Br = Bsh + warp * 375;
    for (int i = lane; i < 375; i += 32) {
        int s1a = i / 25, w2 = i - s1a * 25;
        float2 acc = make_float2(0.f, 0.f);
        int t = 0;
#pragma unroll
        for (int w1 = 0; w1 < 15; w1++) {
            acc = cfma(Grow[(25 * w1 + w2) * 9 + warp], tw15s[t], acc);
            t += s1a; if (t >= 15) t -= 15;
        }
        int u = w2 * s1a;                       // <= 336
        Br[i] = cmul(acc, tw375p[u + (u >> 4)]);
    }
    __syncwarp();

    // Stage B: Y[s1] = sum_w2 B[s1a][w2] e^{+2pi i w2 s1b/25}
    const float inv = 1.0f / (float)NFFT;
    for (int s1 = lane; s1 < 375; s1 += 32) {
        int s1a = s1 % 15, s1b = s1 / 15;
        const float2* Bp = Br + s1a * 25;
        float2 acc = make_float2(0.f, 0.f);
        int t = 0;
#pragma unroll
        for (int w2 = 0; w2 < 25; w2++) {
            acc = cfma(Bp[w2], tw25s[t], acc);
            t += s1b; if (t >= 25) t -= 25;
        }
        ytile[s1 * 9 + warp] = make_float2(acc.x * inv, acc.y * inv);
    }
    __syncthreads();

    float* yT = g_y + (size_t)p * NFFT;
    float* yA = g_y + (size_t)(NB + p) * NFFT;
    for (int i = tid; i < 3000; i += 256) {
        int s1 = i >> 3, j = i & 7;
        float2 v = ytile[s1 * 9 + j];
        yT[256 * s1 + s20 + j] = v.x;
        yA[256 * s1 + s20 + j] = v.y;
    }
}

// ---------------------------------------------------------------------------
// Pass 3: STFT. One warp per frame: pack even/odd into complex-256, 16x16 FFT,
// Hermitian untangle -> |rfft512|^2 -> P[sig][m][f]. Padded shared rows.
// ---------------------------------------------------------------------------
__global__ void __launch_bounds__(256) pass3_kernel() {
    int p  = blockIdx.y;       // signal index 0..255
    int m0 = blockIdx.x * 8;

    __shared__ float2 zsh[8][256];
    __shared__ float2 Ash[8][16 * 17];
    __shared__ float2 ctw16[16];          // e^{-2pi i j/16}
    __shared__ float2 ctw256p[272];       // e^{-2pi i u/256} at u+(u>>4)
    __shared__ float2 tw512s[257];        // e^{-2pi i f/512}
    __shared__ float  wins[512];

    int tid = threadIdx.x, warp = tid >> 5, lane = tid & 31;
    for (int i = tid; i < 512; i += 256) wins[i] = g_win[i];
    for (int i = tid; i < 257; i += 256) tw512s[i] = g_tw512[i];
    if (tid < 16) ctw16[tid] = g_tw512[32 * tid];
    { int u = tid; if (u < 256) ctw256p[u + (u >> 4)] = g_tw512[(2 * u) & 511]; }
    __syncthreads();

    int m = m0 + warp;
    if (m >= TFR) return;

    const float* yp = g_y + (size_t)p * NFFT + 256 * m;
    float2* z  = zsh[warp];
    float2* Aa = Ash[warp];

    for (int i = lane; i < 256; i += 32) {
        float2 yv = *reinterpret_cast<const float2*>(yp + 2 * i);
        float2 wv = *reinterpret_cast<const float2*>(wins + 2 * i);
        z[i] = make_float2(yv.x * wv.x, yv.y * wv.y);
    }
    __syncwarp();

    for (int i = lane; i < 256; i += 32) {
        int ka = i >> 4, m2 = i & 15;
        float2 a0 = make_float2(0.f, 0.f), a1 = make_float2(0.f, 0.f);
#pragma unroll
        for (int m1 = 0; m1 < 16; m1 += 2) {
            a0 = cfma(z[16 * m1 + m2],       ctw16[(m1 * ka) & 15],       a0);
            a1 = cfma(z[16 * (m1 + 1) + m2], ctw16[((m1 + 1) * ka) & 15], a1);
        }
        float2 acc = make_float2(a0.x + a1.x, a0.y + a1.y);
        int u = m2 * ka;                       // <= 225
        Aa[ka * 17 + m2] = cmul(acc, ctw256p[u + (u >> 4)]);
    }
    __syncwarp();

    for (int k = lane; k < 256; k += 32) {
        int ka = k & 15, kb = k >> 4;
        const float2* Arr = Aa + ka * 17;
        float2 a0 = make_float2(0.f, 0.f), a1 = make_float2(0.f, 0.f);
#pragma unroll
        for (int m2 = 0; m2 < 16; m2 += 2) {
            a0 = cfma(Arr[m2],     ctw16[(m2 * kb) & 15],       a0);
            a1 = cfma(Arr[m2 + 1], ctw16[((m2 + 1) * kb) & 15], a1);
        }
        z[k] = make_float2(a0.x + a1.x, a0.y + a1.y);
    }
    __syncwarp();

    float* Pp = g_P + ((size_t)p * TFR + m) * FBIN;
    for (int f = lane; f < FBIN; f += 32) {
        int k  = f & 255;
        int kc = (256 - k) & 255;
        float2 Z1 = z[k], Z2 = z[kc];
        float2 E = make_float2(0.5f * (Z1.x + Z2.x),  0.5f * (Z1.y - Z2.y));
        float2 O = make_float2(0.5f * (Z1.y + Z2.y), -0.5f * (Z1.x - Z2.x));
        float2 Wf = tw512s[f];
        float2 S = make_float2(E.x + Wf.x * O.x - Wf.y * O.y,
                               E.y + Wf.x * O.y + Wf.y * O.x);
        Pp[f] = S.x * S.x + S.y * S.y;
    }
}

// ---------------------------------------------------------------------------
// Pass 4: suffix sums along m, dB, |diff| and |target| partial sums per batch.
// ---------------------------------------------------------------------------
__global__ void __launch_bounds__(288) pass4_kernel() {
    int b = blockIdx.x;
    int f = threadIdx.x;
    double num = 0.0, den = 0.0;
    if (f < FBIN) {
        const float* PT = g_P + (size_t)b * TFR * FBIN + f;
        const float* PA = g_P + (size_t)(NB + b) * TFR * FBIN + f;
        float accT = 0.f, accA = 0.f;
        for (int m = TFR - 1; m >= 0; m--) {
            accT += PT[(size_t)m * FBIN];
            accA += PA[(size_t)m * FBIN];
            float eT = 10.0f * log10f(accT);
            float eA = 10.0f * log10f(accA);
            num += (double)fabsf(eT - eA);
            den += (double)fabsf(eT);
        }
    }
    __shared__ double sn[288], sd[288];
    sn[threadIdx.x] = num;
    sd[threadIdx.x] = den;
    __syncthreads();
    if (threadIdx.x == 0) {
        double a = 0.0, c = 0.0;
        for (int i = 0; i < 288; i++) { a += sn[i]; c += sd[i]; }
        g_pnum[b] = a;
        g_pden[b] = c;
    }
}

__global__ void final_kernel(float* __restrict__ out) {
    double n = 0.0, d = 0.0;
    for (int i = 0; i < 128; i++) { n += g_pnum[i]; d += g_pden[i]; }
    out[0] = (float)(n / d);
}

// ---------------------------------------------------------------------------
extern "C" void kernel_launch(void* const* d_in, const int* in_sizes, int n_in,
                              void* d_out, int out_size) {
    const float* tgt = (const float*)d_in[0];
    const float* ach = (const float*)d_in[1];
    float* out = (float*)d_out;
    (void)in_sizes; (void)n_in; (void)out_size;

    cudaFuncSetAttribute(pass2_kernel, cudaFuncAttributeMaxDynamicSharedMemorySize, P2_SMEM);

    build_tables_kernel<<<(NFFT + 255) / 256, 256>>>();
    pass1_kernel<<<dim3(47, NB), 256>>>(tgt, ach);
    pass2_kernel<<<dim3(NM / 8, NB), 256, P2_SMEM>>>();
    pass3_kernel<<<dim3((TFR + 7) / 8, NSIG), 256>>>();
    pass4_kernel<<<128, 288>>>();
    final_kernel<<<1, 1>>>(out);
}

// round 5
// speedup vs baseline: 2.2900x; 1.1535x over previous
#include <cuda_runtime.h>
#include <math.h>

// ---------------------------------------------------------------------------
// EDR loss: irfft(96000) -> STFT(512/256, hann) -> suffix-sum dB -> L1 ratio
// N = 96000 = 375 * 256.  k = w + 375*m (w<375, m<256); t = 256*s1 + s2.
// Packing: z[k] = Ct[k] + i*Ca[k] (both spectra real & even) -> one complex
// FFT per batch; Re -> target RIR, Im -> achieved RIR.
// 256-pt FFTs: 16x16, each 16-pt done as register FFT-8 per lane + shfl
// combine across lane pairs (lane ^ 16).
// ---------------------------------------------------------------------------

#define NFFT  96000
#define NHALF 48000
#define NB    128          // batches (complex-packed signals)
#define NSIG  256          // 2 * NB real signals
#define NW    375
#define NM    256
#define TFR   374
#define FBIN  257

__device__ float2 g_G[(size_t)NB * NW * NM];        // [p][w][s2]
__device__ float  g_y[(size_t)NSIG * NFFT];         // [sig][t]
__device__ float  g_P[(size_t)NSIG * TFR * FBIN];   // [sig][m][f]
__device__ float2 g_tw96000[NFFT];                  // e^{+2pi i j/96000}
__device__ float2 g_tw512[512];                     // e^{-2pi i j/512}
__device__ float  g_win[512];
__device__ double g_pnum[128];
__device__ double g_pden[128];

__device__ __forceinline__ float2 cadd(float2 a, float2 b) { return make_float2(a.x + b.x, a.y + b.y); }
__device__ __forceinline__ float2 csub(float2 a, float2 b) { return make_float2(a.x - b.x, a.y - b.y); }
__device__ __forceinline__ float2 cmul(float2 a, float2 b) {
    return make_float2(fmaf(a.x, b.x, -a.y * b.y), fmaf(a.x, b.y, a.y * b.x));
}
__device__ __forceinline__ float2 cfma(float2 a, float2 b, float2 c) {
    c.x = fmaf(a.x, b.x, fmaf(-a.y, b.y, c.x));
    c.y = fmaf(a.x, b.y, fmaf( a.y, b.x, c.y));
    return c;
}

// FFT-8 in registers, exponent sign S: F[s] = sum_n v[n] e^{S*2pi i n s/8}
#define RT2H 0.70710678118654752f
template<int S>
__device__ __forceinline__ void fft8(float2 v[8]) {
    float2 e0 = v[0], e1 = v[2], e2 = v[4], e3 = v[6];
    float2 o0 = v[1], o1 = v[3], o2 = v[5], o3 = v[7];
    // FFT4 of evens
    float2 t0 = cadd(e0, e2), t1 = csub(e0, e2), t2 = cadd(e1, e3), t3 = csub(e1, e3);
    float2 r3 = (S > 0) ? make_float2(-t3.y, t3.x) : make_float2(t3.y, -t3.x); // S*i*t3
    float2 E0 = cadd(t0, t2), E2 = csub(t0, t2), E1 = cadd(t1, r3), E3 = csub(t1, r3);
    // FFT4 of odds
    float2 u0 = cadd(o0, o2), u1 = csub(o0, o2), u2 = cadd(o1, o3), u3 = csub(o1, o3);
    float2 s3 = (S > 0) ? make_float2(-u3.y, u3.x) : make_float2(u3.y, -u3.x);
    float2 O0 = cadd(u0, u2), O2 = csub(u0, u2), O1 = cadd(u1, s3), O3 = csub(u1, s3);
    // combine: w8^q
    float2 T0 = O0;
    float2 T1 = make_float2(RT2H * (O1.x - (float)S * O1.y), RT2H * ((float)S * O1.x + O1.y));
    float2 T2 = (S > 0) ? make_float2(-O2.y, O2.x) : make_float2(O2.y, -O2.x);
    float2 T3 = make_float2(-RT2H * (O3.x + (float)S * O3.y), RT2H * ((float)S * O3.x - O3.y));
    v[0] = cadd(E0, T0); v[4] = csub(E0, T0);
    v[1] = cadd(E1, T1); v[5] = csub(E1, T1);
    v[2] = cadd(E2, T2); v[6] = csub(E2, T2);
    v[3] = cadd(E3, T3); v[7] = csub(E3, T3);
}

// FFT-16 across a lane pair (partner = lane ^ 16). On entry v[a] = x[2a+b];
// on exit v[q] = F16[8b+q],  F16[s] = sum_n x[n] e^{S*2pi i n s/16}.
template<int S>
__device__ __forceinline__ void fft16_pair(float2 v[8], int b) {
    const float TWC[8] = {1.0f, 0.9238795325112867f, 0.7071067811865476f, 0.3826834323650898f,
                          0.0f, -0.3826834323650898f, -0.7071067811865476f, -0.9238795325112867f};
    const float TWS[8] = {0.0f, 0.3826834323650898f, 0.7071067811865476f, 0.9238795325112867f,
                          1.0f, 0.9238795325112867f, 0.7071067811865476f, 0.3826834323650898f};
    fft8<S>(v);   // v[q] = H_b[q]
#pragma unroll
    for (int q = 0; q < 8; q++) {
        float2 mine = v[q];
        float2 oth;
        oth.x = __shfl_xor_sync(0xffffffffu, mine.x, 16);
        oth.y = __shfl_xor_sync(0xffffffffu, mine.y, 16);
        float2 H0 = b ? oth : mine;
        float2 H1 = b ? mine : oth;
        float2 tw = make_float2(TWC[q], (float)S * TWS[q]);
        float2 t = cmul(H1, tw);
        v[q] = b ? csub(H0, t) : cadd(H0, t);
    }
}

// ---------------------------------------------------------------------------
__global__ void build_tables_kernel() {
    int i = blockIdx.x * blockDim.x + threadIdx.x;
    if (i < NFFT) {
        double a = (2.0 * M_PI / (double)NFFT) * (double)i;
        g_tw96000[i] = make_float2((float)cos(a), (float)sin(a));
    }
    if (i < 512) {
        double a = (2.0 * M_PI / 512.0) * (double)i;
        g_tw512[i] = make_float2((float)cos(a), (float)-sin(a));
        g_win[i]   = (float)(0.5 * (1.0 - cos(a)));
    }
}

// ---------------------------------------------------------------------------
// Pass 1: per (p, w): G[p][w][s2] = e^{+2pi i w s2/N} * FFT256_m(z[w+375m])[s2]
// ---------------------------------------------------------------------------
__global__ void __launch_bounds__(256) pass1_kernel(const float* __restrict__ tgt,
                                                    const float* __restrict__ ach) {
    __shared__ float2 zsh[8][256];
    __shared__ float2 Ash[8][16 * 17];
    __shared__ float2 tw256p[272];         // e^{+2pi i u/256} at u + (u>>4)

    int p  = blockIdx.y;
    int w0 = blockIdx.x * 8;
    int tid = threadIdx.x, warp = tid >> 5, lane = tid & 31;
    int b = lane >> 4, col = lane & 15;

    { int u = tid; if (u < 256) tw256p[u + (u >> 4)] = g_tw96000[375 * u]; }

    int w = w0 + warp;
    const float* Xt = tgt + (size_t)p * NFFT;
    const float* Xa = ach + (size_t)p * NFFT;
    if (w < NW) {
        for (int m = lane; m < 256; m += 32) {
            int k = w + 375 * m;
            int r = (k <= NHALF) ? k : (NFFT - k);
            zsh[warp][m] = make_float2(__ldg(Xt + r), __ldg(Xa + r));
        }
    }
    __syncthreads();
    if (w >= NW) return;

    const float2* zr = zsh[warp];
    float2* Ar = Ash[warp];
    float2 v[8];

    // Stage A: FFT16 over m1 for column m2=col; output s2a = 8b+q.
#pragma unroll
    for (int a = 0; a < 8; a++) v[a] = zr[32 * a + 16 * b + col];
    fft16_pair<1>(v, b);
#pragma unroll
    for (int q = 0; q < 8; q++) {
        int s = 8 * b + q;
        int u = col * s;                       // <= 225
        Ar[s * 17 + col] = cmul(v[q], tw256p[u + (u >> 4)]);
    }
    __syncwarp();

    // Stage B: FFT16 over m2 for row s2a=col; s2 = row + 16*(8b+q).
#pragma unroll
    for (int a = 0; a < 8; a++) v[a] = Ar[col * 17 + 2 * a + b];
    fft16_pair<1>(v, b);

    // Outer twiddle recurrence + coalesced global store
    float2 t    = g_tw96000[w * (col + 128 * b)];   // <= 374*143 < 96000
    float2 step = g_tw96000[16 * w];
    float2* Gout = g_G + ((size_t)p * NW + w) * NM;
#pragma unroll
    for (int q = 0; q < 8; q++) {
        int s2 = col + 128 * b + 16 * q;
        Gout[s2] = cmul(v[q], t);
        t = cmul(t, step);
    }
}

// ---------------------------------------------------------------------------
// Pass 2: per (p, s2): Y[s1] = sum_w G[p][w][s2] e^{+2pi i w s1/375};
// y_t = Re(Y)/N, y_a = Im(Y)/N.  375 = 15*25.  8 s2 per block.
// ---------------------------------------------------------------------------
#define P2_SMEM ((3375 + 3000 + 3375 + 15 + 25 + 360) * 8)

__global__ void __launch_bounds__(256) pass2_kernel() {
    int p   = blockIdx.y;
    int s20 = blockIdx.x * 8;

    extern __shared__ float2 sm2[];
    float2* Grow   = sm2;                 // [w][j], pad 9
    float2* Bsh    = Grow + 3375;         // [j][375]
    float2* ytile  = Bsh + 3000;          // [s1][j], pad 9
    float2* tw15s  = ytile + 3375;
    float2* tw25s  = tw15s + 15;
    float2* tw375p = tw25s + 25;

    int tid = threadIdx.x, warp = tid >> 5, lane = tid & 31;
    if (tid < 15) tw15s[tid] = g_tw96000[6400 * tid];
    if (tid < 25) tw25s[tid] = g_tw96000[3840 * tid];
    for (int u = tid; u < 337; u += 256) tw375p[u + (u >> 4)] = g_tw96000[256 * u];

    for (int i = tid; i < 3000; i += 256) {
        int w = i >> 3, j = i & 7;
        Grow[w * 9 + j] = g_G[((size_t)p * NW + w) * NM + s20 + j];
    }
    __syncthreads();

    float2* Br = Bsh + warp * 375;
    for (int i = lane; i < 375; i += 32) {
        int s1a = i / 25, w2 = i - s1a * 25;
        float2 acc = make_float2(0.f, 0.f);
        int t = 0;
#pragma unroll
        for (int w1 = 0; w1 < 15; w1++) {
            acc = cfma(Grow[(25 * w1 + w2) * 9 + warp], tw15s[t], acc);
            t += s1a; if (t >= 15) t -= 15;
        }
        int u = w2 * s1a;
        Br[i] = cmul(acc, tw375p[u + (u >> 4)]);
    }
    __syncwarp();

    const float inv = 1.0f / (float)NFFT;
    for (int s1 = lane; s1 < 375; s1 += 32) {
        int s1a = s1 % 15, s1b = s1 / 15;
        const float2* Bp = Br + s1a * 25;
        float2 acc = make_float2(0.f, 0.f);
        int t = 0;
#pragma unroll
        for (int w2 = 0; w2 < 25; w2++) {
            acc = cfma(Bp[w2], tw25s[t], acc);
            t += s1b; if (t >= 25) t -= 25;
        }
        ytile[s1 * 9 + warp] = make_float2(acc.x * inv, acc.y * inv);
    }
    __syncthreads();

    float* yT = g_y + (size_t)p * NFFT;
    float* yA = g_y + (size_t)(NB + p) * NFFT;
    for (int i = tid; i < 3000; i += 256) {
        int s1 = i >> 3, j = i & 7;
        float2 v = ytile[s1 * 9 + j];
        yT[256 * s1 + s20 + j] = v.x;
        yA[256 * s1 + s20 + j] = v.y;
    }
}

// ---------------------------------------------------------------------------
// Pass 3: STFT. One warp per frame: pack even/odd -> complex-256 FFT (16x16,
// register FFT-16s), Hermitian untangle -> |rfft512|^2 -> P[sig][m][f].
// ---------------------------------------------------------------------------
__global__ void __launch_bounds__(256) pass3_kernel() {
    int p  = blockIdx.y;
    int m0 = blockIdx.x * 8;

    __shared__ float2 zsh[8][256];
    __shared__ float2 Ash[8][16 * 17];
    __shared__ float2 ctw256p[272];       // e^{-2pi i u/256} at u+(u>>4)
    __shared__ float2 tw512s[257];        // e^{-2pi i f/512}
    __shared__ float  wins[512];

    int tid = threadIdx.x, warp = tid >> 5, lane = tid & 31;
    int b = lane >> 4, col = lane & 15;
    for (int i = tid; i < 512; i += 256) wins[i] = g_win[i];
    for (int i = tid; i < 257; i += 256) tw512s[i] = g_tw512[i];
    { int u = tid; if (u < 256) ctw256p[u + (u >> 4)] = g_tw512[(2 * u) & 511]; }
    __syncthreads();

    int m = m0 + warp;
    if (m >= TFR) return;

    const float* yp = g_y + (size_t)p * NFFT + 256 * m;
    float2* z  = zsh[warp];
    float2* Aa = Ash[warp];

    for (int i = lane; i < 256; i += 32) {
        float2 yv = *reinterpret_cast<const float2*>(yp + 2 * i);
        float2 wv = *reinterpret_cast<const float2*>(wins + 2 * i);
        z[i] = make_float2(yv.x * wv.x, yv.y * wv.y);
    }
    __syncwarp();

    float2 v[8];
    // Stage A
#pragma unroll
    for (int a = 0; a < 8; a++) v[a] = z[32 * a + 16 * b + col];
    fft16_pair<-1>(v, b);
#pragma unroll
    for (int q = 0; q < 8; q++) {
        int s = 8 * b + q;
        int u = col * s;
        Aa[s * 17 + col] = cmul(v[q], ctw256p[u + (u >> 4)]);
    }
    __syncwarp();

    // Stage B
#pragma unroll
    for (int a = 0; a < 8; a++) v[a] = Aa[col * 17 + 2 * a + b];
    fft16_pair<-1>(v, b);
#pragma unroll
    for (int q = 0; q < 8; q++) {
        int k = col + 128 * b + 16 * q;
        z[k] = v[q];
    }
    __syncwarp();

    float* Pp = g_P + ((size_t)p * TFR + m) * FBIN;
    for (int f = lane; f < FBIN; f += 32) {
        int k  = f & 255;
        int kc = (256 - k) & 255;
        float2 Z1 = z[k], Z2 = z[kc];
        float2 E = make_float2(0.5f * (Z1.x + Z2.x),  0.5f * (Z1.y - Z2.y));
        float2 O = make_float2(0.5f * (Z1.y + Z2.y), -0.5f * (Z1.x - Z2.x));
        float2 Wf = tw512s[f];
        float2 S = make_float2(E.x + Wf.x * O.x - Wf.y * O.y,
                               E.y + Wf.x * O.y + Wf.y * O.x);
        Pp[f] = S.x * S.x + S.y * S.y;
    }
}

// ---------------------------------------------------------------------------
__global__ void __launch_bounds__(288) pass4_kernel() {
    int bidx = blockIdx.x;
    int f = threadIdx.x;
    double num = 0.0, den = 0.0;
    if (f < FBIN) {
        const float* PT = g_P + (size_t)bidx * TFR * FBIN + f;
        const float* PA = g_P + (size_t)(NB + bidx) * TFR * FBIN + f;
        float accT = 0.f, accA = 0.f;
        for (int m = TFR - 1; m >= 0; m--) {
            accT += PT[(size_t)m * FBIN];
            accA += PA[(size_t)m * FBIN];
            float eT = 10.0f * log10f(accT);
            float eA = 10.0f * log10f(accA);
            num += (double)fabsf(eT - eA);
            den += (double)fabsf(eT);
        }
    }
    __shared__ double sn[288], sd[288];
    sn[threadIdx.x] = num;
    sd[threadIdx.x] = den;
    __syncthreads();
    if (threadIdx.x == 0) {
        double a = 0.0, c = 0.0;
        for (int i = 0; i < 288; i++) { a += sn[i]; c += sd[i]; }
        g_pnum[bidx] = a;
        g_pden[bidx] = c;
    }
}

__global__ void final_kernel(float* __restrict__ out) {
    double n = 0.0, d = 0.0;
    for (int i = 0; i < 128; i++) { n += g_pnum[i]; d += g_pden[i]; }
    out[0] = (float)(n / d);
}

// ---------------------------------------------------------------------------
extern "C" void kernel_launch(void* const* d_in, const int* in_sizes, int n_in,
                              void* d_out, int out_size) {
    const float* tgt = (const float*)d_in[0];
    const float* ach = (const float*)d_in[1];
    float* out = (float*)d_out;
    (void)in_sizes; (void)n_in; (void)out_size;

    cudaFuncSetAttribute(pass2_kernel, cudaFuncAttributeMaxDynamicSharedMemorySize, P2_SMEM);

    build_tables_kernel<<<(NFFT + 255) / 256, 256>>>();
    pass1_kernel<<<dim3(47, NB), 256>>>(tgt, ach);
    pass2_kernel<<<dim3(NM / 8, NB), 256, P2_SMEM>>>();
    pass3_kernel<<<dim3((TFR + 7) / 8, NSIG), 256>>>();
    pass4_kernel<<<128, 288>>>();
    final_kernel<<<1, 1>>>(out);
}

// round 6
// speedup vs baseline: 2.9653x; 1.2949x over previous
#include <cuda_runtime.h>
#include <math.h>

// ---------------------------------------------------------------------------
// EDR loss: irfft(96000) -> STFT(512/256, hann) -> suffix-sum dB -> L1 ratio
// N = 96000 = 375 * 256.  k = w + 375*m (w<375, m<256); t = 256*s1 + s2.
// Packing: z[k] = Ct[k] + i*Ca[k] (both spectra real & even) -> one complex
// FFT per batch; Re -> target RIR, Im -> achieved RIR.
// ---------------------------------------------------------------------------

#define NFFT  96000
#define NHALF 48000
#define NB    128          // batches (complex-packed signals)
#define NSIG  256          // 2 * NB real signals
#define NW    375
#define NM    256
#define TFR   374
#define FBIN  257
#define NCH   8            // pass4 chunks
#define CHW   47           // frames per chunk (8*47 >= 374)

__device__ float2 g_G[(size_t)NB * NW * NM];        // [p][w][s2]
__device__ float  g_y[(size_t)NSIG * NFFT];         // [sig][t]
__device__ float  g_P[(size_t)NSIG * TFR * FBIN];   // [sig][m][f]
__device__ float2 g_tw96000[NFFT];                  // e^{+2pi i j/96000}
__device__ float2 g_tw512[512];                     // e^{-2pi i j/512}
__device__ float  g_win[512];
__device__ float  g_csT[128 * NCH * FBIN];          // pass4 chunk sums
__device__ float  g_csA[128 * NCH * FBIN];
__device__ double g_pn[128 * NCH];
__device__ double g_pd[128 * NCH];

__device__ __forceinline__ float2 cadd(float2 a, float2 b) { return make_float2(a.x + b.x, a.y + b.y); }
__device__ __forceinline__ float2 csub(float2 a, float2 b) { return make_float2(a.x - b.x, a.y - b.y); }
__device__ __forceinline__ float2 cmul(float2 a, float2 b) {
    return make_float2(fmaf(a.x, b.x, -a.y * b.y), fmaf(a.x, b.y, a.y * b.x));
}
__device__ __forceinline__ float2 cfma(float2 a, float2 b, float2 c) {
    c.x = fmaf(a.x, b.x, fmaf(-a.y, b.y, c.x));
    c.y = fmaf(a.x, b.y, fmaf( a.y, b.x, c.y));
    return c;
}

// FFT-8 in registers, exponent sign S
#define RT2H 0.70710678118654752f
template<int S>
__device__ __forceinline__ void fft8(float2 v[8]) {
    float2 e0 = v[0], e1 = v[2], e2 = v[4], e3 = v[6];
    float2 o0 = v[1], o1 = v[3], o2 = v[5], o3 = v[7];
    float2 t0 = cadd(e0, e2), t1 = csub(e0, e2), t2 = cadd(e1, e3), t3 = csub(e1, e3);
    float2 r3 = (S > 0) ? make_float2(-t3.y, t3.x) : make_float2(t3.y, -t3.x);
    float2 E0 = cadd(t0, t2), E2 = csub(t0, t2), E1 = cadd(t1, r3), E3 = csub(t1, r3);
    float2 u0 = cadd(o0, o2), u1 = csub(o0, o2), u2 = cadd(o1, o3), u3 = csub(o1, o3);
    float2 s3 = (S > 0) ? make_float2(-u3.y, u3.x) : make_float2(u3.y, -u3.x);
    float2 O0 = cadd(u0, u2), O2 = csub(u0, u2), O1 = cadd(u1, s3), O3 = csub(u1, s3);
    float2 T0 = O0;
    float2 T1 = make_float2(RT2H * (O1.x - (float)S * O1.y), RT2H * ((float)S * O1.x + O1.y));
    float2 T2 = (S > 0) ? make_float2(-O2.y, O2.x) : make_float2(O2.y, -O2.x);
    float2 T3 = make_float2(-RT2H * (O3.x + (float)S * O3.y), RT2H * ((float)S * O3.x - O3.y));
    v[0] = cadd(E0, T0); v[4] = csub(E0, T0);
    v[1] = cadd(E1, T1); v[5] = csub(E1, T1);
    v[2] = cadd(E2, T2); v[6] = csub(E2, T2);
    v[3] = cadd(E3, T3); v[7] = csub(E3, T3);
}

// FFT-16 across lane pair (partner = lane ^ 16). Entry v[a]=x[2a+b]; exit v[q]=F16[8b+q].
template<int S>
__device__ __forceinline__ void fft16_pair(float2 v[8], int b) {
    const float TWC[8] = {1.0f, 0.9238795325112867f, 0.7071067811865476f, 0.3826834323650898f,
                          0.0f, -0.3826834323650898f, -0.7071067811865476f, -0.9238795325112867f};
    const float TWS[8] = {0.0f, 0.3826834323650898f, 0.7071067811865476f, 0.9238795325112867f,
                          1.0f, 0.9238795325112867f, 0.7071067811865476f, 0.3826834323650898f};
    fft8<S>(v);
#pragma unroll
    for (int q = 0; q < 8; q++) {
        float2 mine = v[q];
        float2 oth;
        oth.x = __shfl_xor_sync(0xffffffffu, mine.x, 16);
        oth.y = __shfl_xor_sync(0xffffffffu, mine.y, 16);
        float2 H0 = b ? oth : mine;
        float2 H1 = b ? mine : oth;
        float2 tw = make_float2(TWC[q], (float)S * TWS[q]);
        float2 t = cmul(H1, tw);
        v[q] = b ? csub(H0, t) : cadd(H0, t);
    }
}

// Cephes-style log10f: FMA-only (no MUFU). abs err ~1e-7.
__device__ __forceinline__ float fast_log10(float v) {
    int xi = __float_as_int(v);
    int e = (xi >> 23) - 126;
    float m = __int_as_float((xi & 0x007FFFFF) | 0x3F000000);   // [0.5, 1)
    if (m < 0.70710678f) { m += m; e -= 1; }                    // [0.7071, 1.4142)
    float x = m - 1.0f;
    float z = x * x;
    float p =            7.0376836292e-2f;
    p = fmaf(p, x, -1.1514610310e-1f);
    p = fmaf(p, x,  1.1676998740e-1f);
    p = fmaf(p, x, -1.2420140846e-1f);
    p = fmaf(p, x,  1.4249322787e-1f);
    p = fmaf(p, x, -1.6668057665e-1f);
    p = fmaf(p, x,  2.0000714765e-1f);
    p = fmaf(p, x, -2.4999993993e-1f);
    p = fmaf(p, x,  3.3333331174e-1f);
    float y = x * z * p;
    y = fmaf(-0.5f, z, y);
    float ln1px = x + y;
    return fmaf((float)e, 0.30102999566398f, ln1px * 0.43429448190325f);
}

// ---------------------------------------------------------------------------
__global__ void build_tables_kernel() {
    int i = blockIdx.x * blockDim.x + threadIdx.x;
    if (i < NFFT) {
        double a = (2.0 * M_PI / (double)NFFT) * (double)i;
        g_tw96000[i] = make_float2((float)cos(a), (float)sin(a));
    }
    if (i < 512) {
        double a = (2.0 * M_PI / 512.0) * (double)i;
        g_tw512[i] = make_float2((float)cos(a), (float)-sin(a));
        g_win[i]   = (float)(0.5 * (1.0 - cos(a)));
    }
}

// ---------------------------------------------------------------------------
// Pass 1: per (p, w): G[p][w][s2] = e^{+2pi i w s2/N} * FFT256_m(z[w+375m])[s2]
// ---------------------------------------------------------------------------
__global__ void __launch_bounds__(256) pass1_kernel(const float* __restrict__ tgt,
                                                    const float* __restrict__ ach) {
    __shared__ float2 zsh[8][256];
    __shared__ float2 Ash[8][16 * 17];
    __shared__ float2 tw256p[272];

    int p  = blockIdx.y;
    int w0 = blockIdx.x * 8;
    int tid = threadIdx.x, warp = tid >> 5, lane = tid & 31;
    int b = lane >> 4, col = lane & 15;

    { int u = tid; if (u < 256) tw256p[u + (u >> 4)] = g_tw96000[375 * u]; }

    int w = w0 + warp;
    const float* Xt = tgt + (size_t)p * NFFT;
    const float* Xa = ach + (size_t)p * NFFT;
    if (w < NW) {
        for (int m = lane; m < 256; m += 32) {
            int k = w + 375 * m;
            int r = (k <= NHALF) ? k : (NFFT - k);
            zsh[warp][m] = make_float2(__ldg(Xt + r), __ldg(Xa + r));
        }
    }
    __syncthreads();
    if (w >= NW) return;

    const float2* zr = zsh[warp];
    float2* Ar = Ash[warp];
    float2 v[8];

#pragma unroll
    for (int a = 0; a < 8; a++) v[a] = zr[32 * a + 16 * b + col];
    fft16_pair<1>(v, b);
#pragma unroll
    for (int q = 0; q < 8; q++) {
        int s = 8 * b + q;
        int u = col * s;
        Ar[s * 17 + col] = cmul(v[q], tw256p[u + (u >> 4)]);
    }
    __syncwarp();

#pragma unroll
    for (int a = 0; a < 8; a++) v[a] = Ar[col * 17 + 2 * a + b];
    fft16_pair<1>(v, b);

    float2 t    = g_tw96000[w * (col + 128 * b)];
    float2 step = g_tw96000[16 * w];
    float2* Gout = g_G + ((size_t)p * NW + w) * NM;
#pragma unroll
    for (int q = 0; q < 8; q++) {
        int s2 = col + 128 * b + 16 * q;
        Gout[s2] = cmul(v[q], t);
        t = cmul(t, step);
    }
}

// ---------------------------------------------------------------------------
// Pass 2: per (p, s2): Y[s1] = sum_w G[p][w][s2] e^{+2pi i w s1/375};
// register-blocked DFT-15 (stage A) and DFT-25 (stage B). 8 s2 per block.
// ---------------------------------------------------------------------------
#define P2_SMEM ((3375 + 3000 + 3375 + 15 + 25 + 360) * 8)

__global__ void __launch_bounds__(256) pass2_kernel() {
    int p   = blockIdx.y;
    int s20 = blockIdx.x * 8;

    extern __shared__ float2 sm2[];
    float2* Grow   = sm2;                 // [w][j], pad 9  (3375)
    float2* Bsh    = Grow + 3375;         // [j][s1a*25+w2] (3000)
    float2* ytile  = Bsh + 3000;          // [s1][j], pad 9 (3375)
    float2* tw15s  = ytile + 3375;        // 15
    float2* tw25s  = tw15s + 15;          // 25
    float2* tw375p = tw25s + 25;          // e^{+2pi i u/375} at u+(u>>4)

    int tid = threadIdx.x;
    if (tid < 15) tw15s[tid] = g_tw96000[6400 * tid];
    if (tid < 25) tw25s[tid] = g_tw96000[3840 * tid];
    for (int u = tid; u < 337; u += 256) tw375p[u + (u >> 4)] = g_tw96000[256 * u];

    for (int i = tid; i < 3000; i += 256) {
        int w = i >> 3, j = i & 7;
        Grow[w * 9 + j] = g_G[((size_t)p * NW + w) * NM + s20 + j];
    }
    __syncthreads();

    // Stage A: thread (j, w2): register DFT-15 over w1, all 15 s1a outputs.
    if (tid < 200) {
        int j = tid / 25, w2 = tid - j * 25;
        float2 g[15];
#pragma unroll
        for (int w1 = 0; w1 < 15; w1++) g[w1] = Grow[(25 * w1 + w2) * 9 + j];
#pragma unroll
        for (int s1a = 0; s1a < 15; s1a++) {
            float2 acc = make_float2(0.f, 0.f);
            int t = 0;
#pragma unroll
            for (int w1 = 0; w1 < 15; w1++) {
                acc = cfma(g[w1], tw15s[t], acc);
                t += s1a; if (t >= 15) t -= 15;
            }
            int u = w2 * s1a;                 // <= 336
            Bsh[j * 375 + s1a * 25 + w2] = cmul(acc, tw375p[u + (u >> 4)]);
        }
    }
    __syncthreads();

    // Stage B: thread (j, s1a, h): register DFT-25 over w2, 12-13 s1b outputs.
    const float inv = 1.0f / (float)NFFT;
    if (tid < 240) {
        int j = tid / 30, r = tid - j * 30;
        int s1a = r >> 1, h = r & 1;
        float2 bb[25];
#pragma unroll
        for (int w2 = 0; w2 < 25; w2++) bb[w2] = Bsh[j * 375 + s1a * 25 + w2];
        int lo = h ? 13 : 0, hi = h ? 25 : 13;
        for (int s1b = lo; s1b < hi; s1b++) {
            float2 acc = make_float2(0.f, 0.f);
            int t = 0;
#pragma unroll
            for (int w2 = 0; w2 < 25; w2++) {
                acc = cfma(bb[w2], tw25s[t], acc);
                t += s1b; if (t >= 25) t -= 25;
            }
            int s1 = s1a + 15 * s1b;
            ytile[s1 * 9 + j] = make_float2(acc.x * inv, acc.y * inv);
        }
    }
    __syncthreads();

    float* yT = g_y + (size_t)p * NFFT;
    float* yA = g_y + (size_t)(NB + p) * NFFT;
    for (int i = tid; i < 3000; i += 256) {
        int s1 = i >> 3, j = i & 7;
        float2 v = ytile[s1 * 9 + j];
        yT[256 * s1 + s20 + j] = v.x;
        yA[256 * s1 + s20 + j] = v.y;
    }
}

// ---------------------------------------------------------------------------
// Pass 3: STFT (register FFT-16s) -> |rfft512|^2 -> P[sig][m][f].
// ---------------------------------------------------------------------------
__global__ void __launch_bounds__(256) pass3_kernel() {
    int p  = blockIdx.y;
    int m0 = blockIdx.x * 8;

    __shared__ float2 zsh[8][256];
    __shared__ float2 Ash[8][16 * 17];
    __shared__ float2 ctw256p[272];
    __shared__ float2 tw512s[257];
    __shared__ float  wins[512];

    int tid = threadIdx.x, warp = tid >> 5, lane = tid & 31;
    int b = lane >> 4, col = lane & 15;
    for (int i = tid; i < 512; i += 256) wins[i] = g_win[i];
    for (int i = tid; i < 257; i += 256) tw512s[i] = g_tw512[i];
    { int u = tid; if (u < 256) ctw256p[u + (u >> 4)] = g_tw512[(2 * u) & 511]; }
    __syncthreads();

    int m = m0 + warp;
    if (m >= TFR) return;

    const float* yp = g_y + (size_t)p * NFFT + 256 * m;
    float2* z  = zsh[warp];
    float2* Aa = Ash[warp];

    for (int i = lane; i < 256; i += 32) {
        float2 yv = *reinterpret_cast<const float2*>(yp + 2 * i);
        float2 wv = *reinterpret_cast<const float2*>(wins + 2 * i);
        z[i] = make_float2(yv.x * wv.x, yv.y * wv.y);
    }
    __syncwarp();

    float2 v[8];
#pragma unroll
    for (int a = 0; a < 8; a++) v[a] = z[32 * a + 16 * b + col];
    fft16_pair<-1>(v, b);
#pragma unroll
    for (int q = 0; q < 8; q++) {
        int s = 8 * b + q;
        int u = col * s;
        Aa[s * 17 + col] = cmul(v[q], ctw256p[u + (u >> 4)]);
    }
    __syncwarp();

#pragma unroll
    for (int a = 0; a < 8; a++) v[a] = Aa[col * 17 + 2 * a + b];
    fft16_pair<-1>(v, b);
#pragma unroll
    for (int q = 0; q < 8; q++) {
        int k = col + 128 * b + 16 * q;
        z[k] = v[q];
    }
    __syncwarp();

    float* Pp = g_P + ((size_t)p * TFR + m) * FBIN;
    for (int f = lane; f < FBIN; f += 32) {
        int k  = f & 255;
        int kc = (256 - k) & 255;
        float2 Z1 = z[k], Z2 = z[kc];
        float2 E = make_float2(0.5f * (Z1.x + Z2.x),  0.5f * (Z1.y - Z2.y));
        float2 O = make_float2(0.5f * (Z1.y + Z2.y), -0.5f * (Z1.x - Z2.x));
        float2 Wf = tw512s[f];
        float2 S = make_float2(E.x + Wf.x * O.x - Wf.y * O.y,
                               E.y + Wf.x * O.y + Wf.y * O.x);
        Pp[f] = S.x * S.x + S.y * S.y;
    }
}

// ---------------------------------------------------------------------------
// Pass 4a: per (b, chunk, f): chunk sums of P for target & achieved.
// ---------------------------------------------------------------------------
__global__ void __launch_bounds__(288) pass4a_kernel() {
    int bidx = blockIdx.x, c = blockIdx.y;
    int f = threadIdx.x;
    if (f >= FBIN) return;
    int lo = c * CHW, hi = min(TFR, lo + CHW);
    const float* PT = g_P + (size_t)bidx * TFR * FBIN + f;
    const float* PA = g_P + (size_t)(NB + bidx) * TFR * FBIN + f;
    float sT = 0.f, sA = 0.f;
    for (int m = lo; m < hi; m++) {
        sT += PT[(size_t)m * FBIN];
        sA += PA[(size_t)m * FBIN];
    }
    g_csT[(bidx * NCH + c) * FBIN + f] = sT;
    g_csA[(bidx * NCH + c) * FBIN + f] = sA;
}

// ---------------------------------------------------------------------------
// Pass 4b: per (b, chunk): seed from later chunk sums, walk chunk descending,
// fast log10 (FMA-only), accumulate |diff| and |target| partials.
// ---------------------------------------------------------------------------
__global__ void __launch_bounds__(288) pass4b_kernel() {
    int bidx = blockIdx.x, c = blockIdx.y;
    int f = threadIdx.x;
    double num = 0.0, den = 0.0;
    if (f < FBIN) {
        float accT = 0.f, accA = 0.f;
        for (int c2 = c + 1; c2 < NCH; c2++) {
            accT += g_csT[(bidx * NCH + c2) * FBIN + f];
            accA += g_csA[(bidx * NCH + c2) * FBIN + f];
        }
        int lo = c * CHW, hi = min(TFR, lo + CHW);
        const float* PT = g_P + (size_t)bidx * TFR * FBIN + f;
        const float* PA = g_P + (size_t)(NB + bidx) * TFR * FBIN + f;
        for (int m = hi - 1; m >= lo; m--) {
            accT += PT[(size_t)m * FBIN];
            accA += PA[(size_t)m * FBIN];
            float eT = 10.0f * fast_log10(accT);
            float eA = 10.0f * fast_log10(accA);
            num += (double)fabsf(eT - eA);
            den += (double)fabsf(eT);
        }
    }
    __shared__ double sn[288], sd[288];
    sn[threadIdx.x] = num;
    sd[threadIdx.x] = den;
    __syncthreads();
    if (threadIdx.x == 0) {
        double a = 0.0, d = 0.0;
        for (int i = 0; i < 288; i++) { a += sn[i]; d += sd[i]; }
        g_pn[bidx * NCH + c] = a;
        g_pd[bidx * NCH + c] = d;
    }
}

__global__ void __launch_bounds__(256) final_kernel(float* __restrict__ out) {
    __shared__ double sn[256], sd[256];
    int tid = threadIdx.x;
    double n = 0.0, d = 0.0;
    for (int i = tid; i < 128 * NCH; i += 256) { n += g_pn[i]; d += g_pd[i]; }
    sn[tid] = n; sd[tid] = d;
    __syncthreads();
    if (tid == 0) {
        double a = 0.0, c = 0.0;
        for (int i = 0; i < 256; i++) { a += sn[i]; c += sd[i]; }
        out[0] = (float)(a / c);
    }
}

// ---------------------------------------------------------------------------
extern "C" void kernel_launch(void* const* d_in, const int* in_sizes, int n_in,
                              void* d_out, int out_size) {
    const float* tgt = (const float*)d_in[0];
    const float* ach = (const float*)d_in[1];
    float* out = (float*)d_out;
    (void)in_sizes; (void)n_in; (void)out_size;

    cudaFuncSetAttribute(pass2_kernel, cudaFuncAttributeMaxDynamicSharedMemorySize, P2_SMEM);

    build_tables_kernel<<<(NFFT + 255) / 256, 256>>>();
    pass1_kernel<<<dim3(47, NB), 256>>>(tgt, ach);
    pass2_kernel<<<dim3(NM / 8, NB), 256, P2_SMEM>>>();
    pass3_kernel<<<dim3((TFR + 7) / 8, NSIG), 256>>>();
    pass4a_kernel<<<dim3(128, NCH), 288>>>();
    pass4b_kernel<<<dim3(128, NCH), 288>>>();
    final_kernel<<<1, 256>>>(out);
}

// round 8
// speedup vs baseline: 3.9338x; 1.3266x over previous
#include <cuda_runtime.h>
#include <math.h>

// ---------------------------------------------------------------------------
// EDR loss: irfft(96000) -> STFT(512/256, hann) -> suffix-sum dB -> L1 ratio
// N = 96000 = 375 * 256.  k = w + 375*m (w<375, m<256); t = 256*s1 + s2.
// Packing: z[k] = Ct[k] + i*Ca[k] (both spectra real & even) -> one complex
// FFT per batch; Re -> target RIR, Im -> achieved RIR.
// Time symmetry: y[t] = y[N-t] (cosine series) => P[m] = P[373-m]:
// only frames 0..186 are computed; pass4 mirrors.
// ---------------------------------------------------------------------------

#define NFFT  96000
#define NHALF 48000
#define NB    128          // batches (complex-packed signals)
#define NSIG  256          // 2 * NB real signals
#define NW    375
#define NM    256
#define TFR   374          // logical frames
#define TFR2  187          // stored frames (m <= 186; P[m]=P[373-m])
#define FBIN  257
#define NS1   195          // y needed for s1 = 0..194
#define YSTR  (NS1 * 256)  // 49920
#define NCH   8            // pass4 chunks over logical frames
#define CHW   47

__device__ float2 g_G[(size_t)NB * NW * NM];         // [p][w][s2]
__device__ float  g_y[(size_t)NSIG * YSTR];          // [sig][t], t < 49920
__device__ float  g_P[(size_t)NSIG * TFR2 * FBIN];   // [sig][m][f], m < 187
__device__ float2 g_tw96000[NFFT];                   // e^{+2pi i j/96000}
__device__ float2 g_tw512[512];                      // e^{-2pi i j/512}
__device__ float  g_win[512];
__device__ float  g_csT[128 * NCH * FBIN];
__device__ float  g_csA[128 * NCH * FBIN];
__device__ double g_pn[128 * NCH];
__device__ double g_pd[128 * NCH];

__device__ __forceinline__ float2 cadd(float2 a, float2 b) { return make_float2(a.x + b.x, a.y + b.y); }
__device__ __forceinline__ float2 csub(float2 a, float2 b) { return make_float2(a.x - b.x, a.y - b.y); }
__device__ __forceinline__ float2 cmul(float2 a, float2 b) {
    return make_float2(fmaf(a.x, b.x, -a.y * b.y), fmaf(a.x, b.y, a.y * b.x));
}
__device__ __forceinline__ float2 cfma(float2 a, float2 b, float2 c) {
    c.x = fmaf(a.x, b.x, fmaf(-a.y, b.y, c.x));
    c.y = fmaf(a.x, b.y, fmaf( a.y, b.x, c.y));
    return c;
}

#define RT2H 0.70710678118654752f
template<int S>
__device__ __forceinline__ void fft8(float2 v[8]) {
    float2 e0 = v[0], e1 = v[2], e2 = v[4], e3 = v[6];
    float2 o0 = v[1], o1 = v[3], o2 = v[5], o3 = v[7];
    float2 t0 = cadd(e0, e2), t1 = csub(e0, e2), t2 = cadd(e1, e3), t3 = csub(e1, e3);
    float2 r3 = (S > 0) ? make_float2(-t3.y, t3.x) : make_float2(t3.y, -t3.x);
    float2 E0 = cadd(t0, t2), E2 = csub(t0, t2), E1 = cadd(t1, r3), E3 = csub(t1, r3);
    float2 u0 = cadd(o0, o2), u1 = csub(o0, o2), u2 = cadd(o1, o3), u3 = csub(o1, o3);
    float2 s3 = (S > 0) ? make_float2(-u3.y, u3.x) : make_float2(u3.y, -u3.x);
    float2 O0 = cadd(u0, u2), O2 = csub(u0, u2), O1 = cadd(u1, s3), O3 = csub(u1, s3);
    float2 T0 = O0;
    float2 T1 = make_float2(RT2H * (O1.x - (float)S * O1.y), RT2H * ((float)S * O1.x + O1.y));
    float2 T2 = (S > 0) ? make_float2(-O2.y, O2.x) : make_float2(O2.y, -O2.x);
    float2 T3 = make_float2(-RT2H * (O3.x + (float)S * O3.y), RT2H * ((float)S * O3.x - O3.y));
    v[0] = cadd(E0, T0); v[4] = csub(E0, T0);
    v[1] = cadd(E1, T1); v[5] = csub(E1, T1);
    v[2] = cadd(E2, T2); v[6] = csub(E2, T2);
    v[3] = cadd(E3, T3); v[7] = csub(E3, T3);
}

// FFT-16 across lane pair (partner = lane ^ 16). Entry v[a]=x[2a+b]; exit v[q]=F16[8b+q].
template<int S>
__device__ __forceinline__ void fft16_pair(float2 v[8], int b) {
    const float TWC[8] = {1.0f, 0.9238795325112867f, 0.7071067811865476f, 0.3826834323650898f,
                          0.0f, -0.3826834323650898f, -0.7071067811865476f, -0.9238795325112867f};
    const float TWS[8] = {0.0f, 0.3826834323650898f, 0.7071067811865476f, 0.9238795325112867f,
                          1.0f, 0.9238795325112867f, 0.7071067811865476f, 0.3826834323650898f};
    fft8<S>(v);
#pragma unroll
    for (int q = 0; q < 8; q++) {
        float2 mine = v[q];
        float2 oth;
        oth.x = __shfl_xor_sync(0xffffffffu, mine.x, 16);
        oth.y = __shfl_xor_sync(0xffffffffu, mine.y, 16);
        float2 H0 = b ? oth : mine;
        float2 H1 = b ? mine : oth;
        float2 tw = make_float2(TWC[q], (float)S * TWS[q]);
        float2 t = cmul(H1, tw);
        v[q] = b ? csub(H0, t) : cadd(H0, t);
    }
}

// Cephes-style log10f: FMA-only (no MUFU). abs err ~1e-7.
__device__ __forceinline__ float fast_log10(float v) {
    int xi = __float_as_int(v);
    int e = (xi >> 23) - 126;
    float m = __int_as_float((xi & 0x007FFFFF) | 0x3F000000);
    if (m < 0.70710678f) { m += m; e -= 1; }
    float x = m - 1.0f;
    float z = x * x;
    float p =            7.0376836292e-2f;
    p = fmaf(p, x, -1.1514610310e-1f);
    p = fmaf(p, x,  1.1676998740e-1f);
    p = fmaf(p, x, -1.2420140846e-1f);
    p = fmaf(p, x,  1.4249322787e-1f);
    p = fmaf(p, x, -1.6668057665e-1f);
    p = fmaf(p, x,  2.0000714765e-1f);
    p = fmaf(p, x, -2.4999993993e-1f);
    p = fmaf(p, x,  3.3333331174e-1f);
    float y = x * z * p;
    y = fmaf(-0.5f, z, y);
    float ln1px = x + y;
    return fmaf((float)e, 0.30102999566398f, ln1px * 0.43429448190325f);
}

// ---------------------------------------------------------------------------
__global__ void build_tables_kernel() {
    int i = blockIdx.x * blockDim.x + threadIdx.x;
    if (i < NFFT) {
        double a = (2.0 * M_PI / (double)NFFT) * (double)i;
        double s, c;
        sincos(a, &s, &c);
        g_tw96000[i] = make_float2((float)c, (float)s);
    }
    if (i < 512) {
        double a = (2.0 * M_PI / 512.0) * (double)i;
        double s, c;
        sincos(a, &s, &c);
        g_tw512[i] = make_float2((float)c, (float)-s);
        g_win[i]   = (float)(0.5 * (1.0 - c));
    }
}

// ---------------------------------------------------------------------------
// Pass 1: per (p, w): G[p][w][s2] = e^{+2pi i w s2/N} * FFT256_m(z[w+375m])[s2]
// ---------------------------------------------------------------------------
__global__ void __launch_bounds__(256) pass1_kernel(const float* __restrict__ tgt,
                                                    const float* __restrict__ ach) {
    __shared__ float2 zsh[8][256];
    __shared__ float2 Ash[8][16 * 17];
    __shared__ float2 tw256p[272];

    int p  = blockIdx.y;
    int w0 = blockIdx.x * 8;
    int tid = threadIdx.x, warp = tid >> 5, lane = tid & 31;
    int b = lane >> 4, col = lane & 15;

    { int u = tid; if (u < 256) tw256p[u + (u >> 4)] = g_tw96000[375 * u]; }

    int w = w0 + warp;
    const float* Xt = tgt + (size_t)p * NFFT;
    const float* Xa = ach + (size_t)p * NFFT;
    if (w < NW) {
        for (int m = lane; m < 256; m += 32) {
            int k = w + 375 * m;
            int r = (k <= NHALF) ? k : (NFFT - k);
            zsh[warp][m] = make_float2(__ldg(Xt + r), __ldg(Xa + r));
        }
    }
    __syncthreads();
    if (w >= NW) return;

    const float2* zr = zsh[warp];
    float2* Ar = Ash[warp];
    float2 v[8];

#pragma unroll
    for (int a = 0; a < 8; a++) v[a] = zr[32 * a + 16 * b + col];
    fft16_pair<1>(v, b);
#pragma unroll
    for (int q = 0; q < 8; q++) {
        int s = 8 * b + q;
        int u = col * s;
        Ar[s * 17 + col] = cmul(v[q], tw256p[u + (u >> 4)]);
    }
    __syncwarp();

#pragma unroll
    for (int a = 0; a < 8; a++) v[a] = Ar[col * 17 + 2 * a + b];
    fft16_pair<1>(v, b);

    float2 t    = g_tw96000[w * (col + 128 * b)];
    float2 step = g_tw96000[16 * w];
    float2* Gout = g_G + ((size_t)p * NW + w) * NM;
#pragma unroll
    for (int q = 0; q < 8; q++) {
        int s2 = col + 128 * b + 16 * q;
        Gout[s2] = cmul(v[q], t);
        t = cmul(t, step);
    }
}

// ---------------------------------------------------------------------------
// Pass 2: per (p, s2): Y[s1] = sum_w G[p][w][s2] e^{+2pi i w s1/375}, but only
// s1 <= 194 is needed (time symmetry). Register-blocked DFT-15 / DFT-25.
// ---------------------------------------------------------------------------
#define P2_SMEM ((3375 + 3000 + NS1 * 9 + 15 + 25 + 360) * 8)

__global__ void __launch_bounds__(256) pass2_kernel() {
    int p   = blockIdx.y;
    int s20 = blockIdx.x * 8;

    extern __shared__ float2 sm2[];
    float2* Grow   = sm2;                 // [w][j], pad 9  (3375)
    float2* Bsh    = Grow + 3375;         // [j][s1a*25+w2] (3000)
    float2* ytile  = Bsh + 3000;          // [s1][j], pad 9 (NS1*9)
    float2* tw15s  = ytile + NS1 * 9;     // 15
    float2* tw25s  = tw15s + 15;          // 25
    float2* tw375p = tw25s + 25;          // e^{+2pi i u/375} at u+(u>>4)

    int tid = threadIdx.x;
    if (tid < 15) tw15s[tid] = g_tw96000[6400 * tid];
    if (tid < 25) tw25s[tid] = g_tw96000[3840 * tid];
    for (int u = tid; u < 337; u += 256) tw375p[u + (u >> 4)] = g_tw96000[256 * u];

    for (int i = tid; i < 3000; i += 256) {
        int w = i >> 3, j = i & 7;
        Grow[w * 9 + j] = g_G[((size_t)p * NW + w) * NM + s20 + j];
    }
    __syncthreads();

    // Stage A: thread (j, w2): register DFT-15 over w1, all 15 s1a outputs.
    if (tid < 200) {
        int j = tid / 25, w2 = tid - j * 25;
        float2 g[15];
#pragma unroll
        for (int w1 = 0; w1 < 15; w1++) g[w1] = Grow[(25 * w1 + w2) * 9 + j];
#pragma unroll
        for (int s1a = 0; s1a < 15; s1a++) {
            float2 acc = make_float2(0.f, 0.f);
            int t = 0;
#pragma unroll
            for (int w1 = 0; w1 < 15; w1++) {
                acc = cfma(g[w1], tw15s[t], acc);
                t += s1a; if (t >= 15) t -= 15;
            }
            int u = w2 * s1a;
            Bsh[j * 375 + s1a * 25 + w2] = cmul(acc, tw375p[u + (u >> 4)]);
        }
    }
    __syncthreads();

    // Stage B: thread (j, s1a, h): register DFT-25 over w2, s1b in 0..12 only.
    const float inv = 1.0f / (float)NFFT;
    if (tid < 240) {
        int j = tid / 30, r = tid - j * 30;
        int s1a = r >> 1, h = r & 1;
        float2 bb[25];
#pragma unroll
        for (int w2 = 0; w2 < 25; w2++) bb[w2] = Bsh[j * 375 + s1a * 25 + w2];
        int lo = h ? 7 : 0, hi = h ? 13 : 7;
        for (int s1b = lo; s1b < hi; s1b++) {
            float2 acc = make_float2(0.f, 0.f);
            int t = 0;
#pragma unroll
            for (int w2 = 0; w2 < 25; w2++) {
                acc = cfma(bb[w2], tw25s[t], acc);
                t += s1b; if (t >= 25) t -= 25;
            }
            int s1 = s1a + 15 * s1b;          // 0..194
            ytile[s1 * 9 + j] = make_float2(acc.x * inv, acc.y * inv);
        }
    }
    __syncthreads();

    float* yT = g_y + (size_t)p * YSTR;
    float* yA = g_y + (size_t)(NB + p) * YSTR;
    for (int i = tid; i < NS1 * 8; i += 256) {
        int s1 = i >> 3, j = i & 7;
        float2 v = ytile[s1 * 9 + j];
        yT[256 * s1 + s20 + j] = v.x;
        yA[256 * s1 + s20 + j] = v.y;
    }
}

// ---------------------------------------------------------------------------
// Pass 3: STFT frames m = 0..186 only (P[m] = P[373-m]).
// ---------------------------------------------------------------------------
__global__ void __launch_bounds__(256) pass3_kernel() {
    int p  = blockIdx.y;
    int m0 = blockIdx.x * 8;

    __shared__ float2 zsh[8][256];
    __shared__ float2 Ash[8][16 * 17];
    __shared__ float2 ctw256p[272];
    __shared__ float2 tw512s[257];
    __shared__ float  wins[512];

    int tid = threadIdx.x, warp = tid >> 5, lane = tid & 31;
    int b = lane >> 4, col = lane & 15;
    for (int i = tid; i < 512; i += 256) wins[i] = g_win[i];
    for (int i = tid; i < 257; i += 256) tw512s[i] = g_tw512[i];
    { int u = tid; if (u < 256) ctw256p[u + (u >> 4)] = g_tw512[(2 * u) & 511]; }
    __syncthreads();

    int m = m0 + warp;
    if (m >= TFR2) return;

    const float* yp = g_y + (size_t)p * YSTR + 256 * m;
    float2* z  = zsh[warp];
    float2* Aa = Ash[warp];

    for (int i = lane; i < 256; i += 32) {
        float2 yv = *reinterpret_cast<const float2*>(yp + 2 * i);
        float2 wv = *reinterpret_cast<const float2*>(wins + 2 * i);
        z[i] = make_float2(yv.x * wv.x, yv.y * wv.y);
    }
    __syncwarp();

    float2 v[8];
#pragma unroll
    for (int a = 0; a < 8; a++) v[a] = z[32 * a + 16 * b + col];
    fft16_pair<-1>(v, b);
#pragma unroll
    for (int q = 0; q < 8; q++) {
        int s = 8 * b + q;
        int u = col * s;
        Aa[s * 17 + col] = cmul(v[q], ctw256p[u + (u >> 4)]);
    }
    __syncwarp();

#pragma unroll
    for (int a = 0; a < 8; a++) v[a] = Aa[col * 17 + 2 * a + b];
    fft16_pair<-1>(v, b);
#pragma unroll
    for (int q = 0; q < 8; q++) {
        int k = col + 128 * b + 16 * q;
        z[k] = v[q];
    }
    __syncwarp();

    float* Pp = g_P + ((size_t)p * TFR2 + m) * FBIN;
    for (int f = lane; f < FBIN; f += 32) {
        int k  = f & 255;
        int kc = (256 - k) & 255;
        float2 Z1 = z[k], Z2 = z[kc];
        float2 E = make_float2(0.5f * (Z1.x + Z2.x),  0.5f * (Z1.y - Z2.y));
        float2 O = make_float2(0.5f * (Z1.y + Z2.y), -0.5f * (Z1.x - Z2.x));
        float2 Wf = tw512s[f];
        float2 S = make_float2(E.x + Wf.x * O.x - Wf.y * O.y,
                               E.y + Wf.x * O.y + Wf.y * O.x);
        Pp[f] = S.x * S.x + S.y * S.y;
    }
}

// ---------------------------------------------------------------------------
// Pass 4a: per (b, chunk, f): chunk sums over logical frames (mirrored index).
// ---------------------------------------------------------------------------
__global__ void __launch_bounds__(288) pass4a_kernel() {
    int bidx = blockIdx.x, c = blockIdx.y;
    int f = threadIdx.x;
    if (f >= FBIN) return;
    int lo = c * CHW, hi = min(TFR, lo + CHW);
    const float* PT = g_P + (size_t)bidx * TFR2 * FBIN + f;
    const float* PA = g_P + (size_t)(NB + bidx) * TFR2 * FBIN + f;
    float sT = 0.f, sA = 0.f;
    for (int m = lo; m < hi; m++) {
        int pm = (m < TFR2) ? m : (TFR - 1 - m);
        sT += PT[(size_t)pm * FBIN];
        sA += PA[(size_t)pm * FBIN];
    }
    g_csT[(bidx * NCH + c) * FBIN + f] = sT;
    g_csA[(bidx * NCH + c) * FBIN + f] = sA;
}

// ---------------------------------------------------------------------------
// Pass 4b: per (b, chunk): seed from later chunks, walk descending (mirrored),
// fast log10, accumulate |diff| and |target| partials.
// ---------------------------------------------------------------------------
__global__ void __launch_bounds__(288) pass4b_kernel() {
    int bidx = blockIdx.x, c = blockIdx.y;
    int f = threadIdx.x;
    double num = 0.0, den = 0.0;
    if (f < FBIN) {
        float accT = 0.f, accA = 0.f;
        for (int c2 = c + 1; c2 < NCH; c2++) {
            accT += g_csT[(bidx * NCH + c2) * FBIN + f];
            accA += g_csA[(bidx * NCH + c2) * FBIN + f];
        }
        int lo = c * CHW, hi = min(TFR, lo + CHW);
        const float* PT = g_P + (size_t)bidx * TFR2 * FBIN + f;
        const float* PA = g_P + (size_t)(NB + bidx) * TFR2 * FBIN + f;
        for (int m = hi - 1; m >= lo; m--) {
            int pm = (m < TFR2) ? m : (TFR - 1 - m);
            accT += PT[(size_t)pm * FBIN];
            accA += PA[(size_t)pm * FBIN];
            float eT = 10.0f * fast_log10(accT);
            float eA = 10.0f * fast_log10(accA);
            num += (double)fabsf(eT - eA);
            den += (double)fabsf(eT);
        }
    }
    __shared__ double sn[288], sd[288];
    sn[threadIdx.x] = num;
    sd[threadIdx.x] = den;
    __syncthreads();
    if (threadIdx.x == 0) {
        double a = 0.0, d = 0.0;
        for (int i = 0; i < 288; i++) { a += sn[i]; d += sd[i]; }
        g_pn[bidx * NCH + c] = a;
        g_pd[bidx * NCH + c] = d;
    }
}

__global__ void __launch_bounds__(256) final_kernel(float* __restrict__ out) {
    __shared__ double sn[256], sd[256];
    int tid = threadIdx.x;
    double n = 0.0, d = 0.0;
    for (int i = tid; i < 128 * NCH; i += 256) { n += g_pn[i]; d += g_pd[i]; }
    sn[tid] = n; sd[tid] = d;
    __syncthreads();
    if (tid == 0) {
        double a = 0.0, c = 0.0;
        for (int i = 0; i < 256; i++) { a += sn[i]; c += sd[i]; }
        out[0] = (float)(a / c);
    }
}

// ---------------------------------------------------------------------------
extern "C" void kernel_launch(void* const* d_in, const int* in_sizes, int n_in,
                              void* d_out, int out_size) {
    const float* tgt = (const float*)d_in[0];
    const float* ach = (const float*)d_in[1];
    float* out = (float*)d_out;
    (void)in_sizes; (void)n_in; (void)out_size;

    cudaFuncSetAttribute(pass2_kernel, cudaFuncAttributeMaxDynamicSharedMemorySize, P2_SMEM);

    build_tables_kernel<<<(NFFT + 255) / 256, 256>>>();
    pass1_kernel<<<dim3(47, NB), 256>>>(tgt, ach);
    pass2_kernel<<<dim3(NM / 8, NB), 256, P2_SMEM>>>();
    pass3_kernel<<<dim3((TFR2 + 7) / 8, NSIG), 256>>>();
    pass4a_kernel<<<dim3(128, NCH), 288>>>();
    pass4b_kernel<<<dim3(128, NCH), 288>>>();
    final_kernel<<<1, 256>>>(out);
}